// round 1
// baseline (speedup 1.0000x reference)
#include <cuda_runtime.h>
#include <cuda_bf16.h>

// FeatureSim: attn[b,i,j] = softmax_j( sum_k w[k]*|x[b,i,k]-x[b,j,k]| ), key mask j < len[b].
// B=8, L=1024, F=16 (only first 11 features used), out = float32 [8,1024,1024].
//
// Strategy: FMA-pipe-bound problem. Each thread owns 4 consecutive key columns
// (key vectors live in registers, loaded once per block and reused across BQ rows).
// Queries staged in smem. One block sum-reduction per row (max-subtraction skipped:
// scores provably bounded |s| < ~10, exp safe in fp32). One __syncthreads per row
// via double-buffered per-warp partials. Vectorized float4 output stores.

#define L_SEQ 1024
#define FDIM  16
#define NF    11
#define BQ    16            // rows (queries) per block
#define TPB   256           // threads per block; each owns 4 consecutive cols
#define BPB   (L_SEQ / BQ)  // 64 blocks per batch

__global__ __launch_bounds__(TPB)
void featsim_kernel(const float* __restrict__ x,
                    const int*   __restrict__ lens,
                    const float* __restrict__ w,
                    float*       __restrict__ out)
{
    const int b    = blockIdx.x / BPB;
    const int rb   = blockIdx.x % BPB;
    const int i0   = rb * BQ;
    const int tid  = threadIdx.x;
    const int lane = tid & 31;
    const int warp = tid >> 5;

    __shared__ float sq[BQ][12];     // queries: 12 floats/row (11 used, padded)
    __shared__ float red[2][8];      // double-buffered per-warp partial sums

    // Stage this block's BQ query vectors into smem (192 scalar loads).
    if (tid < BQ * 12) {
        int r = tid / 12, k = tid % 12;
        sq[r][k] = x[(size_t)(b * L_SEQ + i0 + r) * FDIM + k];
    }

    // Weights (broadcast loads, L2/L1 resident).
    float wv[NF];
#pragma unroll
    for (int k = 0; k < NF; ++k) wv[k] = w[k];

    // Keys: this thread owns columns j0..j0+3. Load 12 floats per key row
    // via 3 float4 loads (element 11..11 only used; index 11 of the load discarded).
    const int j0 = tid * 4;
    float kk[4][NF];
#pragma unroll
    for (int cc = 0; cc < 4; ++cc) {
        const float4* kp = reinterpret_cast<const float4*>(
            x + (size_t)(b * L_SEQ + j0 + cc) * FDIM);
        float4 a = kp[0], c = kp[1], d = kp[2];
        kk[cc][0] = a.x;  kk[cc][1] = a.y;  kk[cc][2]  = a.z;  kk[cc][3] = a.w;
        kk[cc][4] = c.x;  kk[cc][5] = c.y;  kk[cc][6]  = c.z;  kk[cc][7] = c.w;
        kk[cc][8] = d.x;  kk[cc][9] = d.y;  kk[cc][10] = d.z;
    }

    const int len = lens[b];
    bool valid[4];
#pragma unroll
    for (int cc = 0; cc < 4; ++cc) valid[cc] = (j0 + cc) < len;

    __syncthreads();

    float4* out4 = reinterpret_cast<float4*>(out + (size_t)(b * L_SEQ + i0) * L_SEQ);

    for (int r = 0; r < BQ; ++r) {
        float q[NF];
#pragma unroll
        for (int k = 0; k < NF; ++k) q[k] = sq[r][k];

        float e[4];
        float ps = 0.f;
#pragma unroll
        for (int cc = 0; cc < 4; ++cc) {
            float s = 0.f;
#pragma unroll
            for (int k = 0; k < NF; ++k)
                s = fmaf(wv[k], fabsf(q[k] - kk[cc][k]), s);
            // Scores bounded (|s| < ~10): exp without max-shift is safe in fp32.
            float ev = valid[cc] ? __expf(s) : 0.f;
            e[cc] = ev;
            ps += ev;
        }

        // Warp butterfly reduce: every lane holds the warp sum.
#pragma unroll
        for (int o = 16; o > 0; o >>= 1)
            ps += __shfl_xor_sync(0xffffffffu, ps, o);
        if (lane == 0) red[r & 1][warp] = ps;
        __syncthreads();
        // All threads sum the 8 warp partials (broadcast LDS).
        float tot = 0.f;
#pragma unroll
        for (int t = 0; t < 8; ++t) tot += red[r & 1][t];

        // len >= 1 always => tot > 0; no NaN path needed.
        float inv = 1.0f / tot;

        out4[(size_t)r * (L_SEQ / 4) + tid] =
            make_float4(e[0] * inv, e[1] * inv, e[2] * inv, e[3] * inv);
    }
}

extern "C" void kernel_launch(void* const* d_in, const int* in_sizes, int n_in,
                              void* d_out, int out_size)
{
    const float* x    = (const float*)d_in[0];   // [8,1024,16] f32
    const int*   lens = (const int*)d_in[1];     // [8] i32
    const float* w    = (const float*)d_in[2];   // [11] f32
    float*       out  = (float*)d_out;           // [8,1024,1024] f32

    const int B = 8;
    dim3 grid(B * BPB);   // 512 blocks
    dim3 block(TPB);
    featsim_kernel<<<grid, block>>>(x, lens, w, out);
}

// round 2
// speedup vs baseline: 1.0702x; 1.0702x over previous
#include <cuda_runtime.h>
#include <cuda_bf16.h>

// FeatureSim: attn[b,i,j] = softmax_j( sum_k w[k]*|x[b,i,k]-x[b,j,k]| ), mask j < len[b].
// B=8, L=1024, F=16 (first 11 used), out f32 [8,1024,1024].
//
// R2: packed f32x2 math (Blackwell FFMA2) — diff via add.rn.f32x2 on pre-negated keys,
// abs via 64-bit AND (2x LOP3 on the idle ALU pipe), weighted accumulate via fma.rn.f32x2.
// Halves FMA-pipe load vs scalar. Barriers cut 16 -> 3 by staging unnormalized e in a
// thread-private smem slab (same-thread write/read: no barrier needed) and reducing
// 8 rows per __syncthreads via per-warp partials.

#define L_SEQ 1024
#define FDIM  16
#define NF    11
#define BQ    16            // rows per block
#define CH    8             // rows per reduction chunk
#define TPB   256           // each thread owns 4 consecutive key columns (2 packed pairs)
#define BPB   (L_SEQ / BQ)  // 64 blocks per batch

typedef unsigned long long u64;

__device__ __forceinline__ u64 pack2(float lo, float hi) {
    u64 r; asm("mov.b64 %0, {%1, %2};" : "=l"(r) : "f"(lo), "f"(hi)); return r;
}
__device__ __forceinline__ void unpack2(u64 v, float& lo, float& hi) {
    asm("mov.b64 {%0, %1}, %2;" : "=f"(lo), "=f"(hi) : "l"(v));
}
__device__ __forceinline__ u64 add2(u64 a, u64 b) {
    u64 r; asm("add.rn.f32x2 %0, %1, %2;" : "=l"(r) : "l"(a), "l"(b)); return r;
}
__device__ __forceinline__ u64 fma2(u64 a, u64 b, u64 c) {
    u64 r; asm("fma.rn.f32x2 %0, %1, %2, %3;" : "=l"(r) : "l"(a), "l"(b), "l"(c)); return r;
}

__global__ __launch_bounds__(TPB)
void featsim_kernel(const float* __restrict__ x,
                    const int*   __restrict__ lens,
                    const float* __restrict__ w,
                    float*       __restrict__ out)
{
    const int b    = blockIdx.x / BPB;
    const int rb   = blockIdx.x % BPB;
    const int i0   = rb * BQ;
    const int tid  = threadIdx.x;
    const int lane = tid & 31;
    const int warp = tid >> 5;
    const int j0   = tid * 4;

    __shared__ u64   sq2[BQ][NF];      // queries, duplicated into both f32x2 halves
    __shared__ float se[CH][L_SEQ];    // thread-private e staging (32 KB), no barrier needed
    __shared__ float red[2][CH][8];    // per-warp partial sums, per chunk

    // Stage queries: sq2[r][k] = {q, q}
    for (int idx = tid; idx < BQ * NF; idx += TPB) {
        int r = idx / NF, k = idx - r * NF;
        float q = x[(size_t)(b * L_SEQ + i0 + r) * FDIM + k];
        sq2[r][k] = pack2(q, q);
    }

    // Packed weights {w_k, w_k}
    u64 w2[NF];
#pragma unroll
    for (int k = 0; k < NF; ++k) { float wv = w[k]; w2[k] = pack2(wv, wv); }

    // Keys: 4 cols -> 2 packed pairs, negated so diff = add2(q, nkk).
    float kk[4][NF];
#pragma unroll
    for (int cc = 0; cc < 4; ++cc) {
        const float4* kp = reinterpret_cast<const float4*>(
            x + (size_t)(b * L_SEQ + j0 + cc) * FDIM);
        float4 a = kp[0], c = kp[1], d = kp[2];
        kk[cc][0] = a.x;  kk[cc][1] = a.y;  kk[cc][2]  = a.z;  kk[cc][3] = a.w;
        kk[cc][4] = c.x;  kk[cc][5] = c.y;  kk[cc][6]  = c.z;  kk[cc][7] = c.w;
        kk[cc][8] = d.x;  kk[cc][9] = d.y;  kk[cc][10] = d.z;
    }
    u64 nkk[2][NF];
#pragma unroll
    for (int p = 0; p < 2; ++p)
#pragma unroll
        for (int k = 0; k < NF; ++k)
            nkk[p][k] = pack2(-kk[2 * p][k], -kk[2 * p + 1][k]);

    const int len = lens[b];
    bool valid[4];
#pragma unroll
    for (int cc = 0; cc < 4; ++cc) valid[cc] = (j0 + cc) < len;

    __syncthreads();

    float4* out4 = reinterpret_cast<float4*>(out + (size_t)(b * L_SEQ + i0) * L_SEQ);
    const u64 ABSM = 0x7FFFFFFF7FFFFFFFULL;

    for (int c = 0; c < 2; ++c) {
        // ---- compute chunk: scores + exp + stage e + per-warp partial sums ----
        for (int r = 0; r < CH; ++r) {
            const int rr = c * CH + r;
            u64 s0 = 0ULL, s1 = 0ULL;   // packed {score_c0,score_c1}, {score_c2,score_c3}
#pragma unroll
            for (int k = 0; k < NF; ++k) {
                u64 qq = sq2[rr][k];                 // LDS.64 broadcast
                u64 d0 = add2(qq, nkk[0][k]);        // fma pipe
                u64 d1 = add2(qq, nkk[1][k]);
                d0 &= ABSM;                          // 2x LOP3, alu pipe
                d1 &= ABSM;
                s0 = fma2(w2[k], d0, s0);            // fma pipe
                s1 = fma2(w2[k], d1, s1);
            }
            float f0, f1, f2, f3;
            unpack2(s0, f0, f1);
            unpack2(s1, f2, f3);
            // scores bounded (|s| < ~10): exp without max-shift is safe in fp32
            float e0 = valid[0] ? __expf(f0) : 0.f;
            float e1 = valid[1] ? __expf(f1) : 0.f;
            float e2 = valid[2] ? __expf(f2) : 0.f;
            float e3 = valid[3] ? __expf(f3) : 0.f;

            *reinterpret_cast<float4*>(&se[r][j0]) = make_float4(e0, e1, e2, e3);

            float ps = (e0 + e1) + (e2 + e3);
#pragma unroll
            for (int o = 16; o > 0; o >>= 1)
                ps += __shfl_xor_sync(0xffffffffu, ps, o);
            if (lane == 0) red[c][r][warp] = ps;
        }
        __syncthreads();   // red[c] now visible block-wide

        // ---- normalize chunk ----
        for (int r = 0; r < CH; ++r) {
            const int rr = c * CH + r;
            float tot = 0.f;
#pragma unroll
            for (int t = 0; t < 8; ++t) tot += red[c][r][t];
            float inv;
            asm("rcp.approx.f32 %0, %1;" : "=f"(inv) : "f"(tot));  // len>=1 => tot>0

            float4 ev = *reinterpret_cast<float4*>(&se[r][j0]);
            out4[(size_t)rr * (L_SEQ / 4) + tid] =
                make_float4(ev.x * inv, ev.y * inv, ev.z * inv, ev.w * inv);
        }
        // se is thread-private (same thread writes & reads its 16B slot) -> no barrier
        // red is chunk-indexed -> no barrier before next chunk's writes
    }
}

extern "C" void kernel_launch(void* const* d_in, const int* in_sizes, int n_in,
                              void* d_out, int out_size)
{
    const float* x    = (const float*)d_in[0];   // [8,1024,16] f32
    const int*   lens = (const int*)d_in[1];     // [8] i32
    const float* w    = (const float*)d_in[2];   // [11] f32
    float*       out  = (float*)d_out;           // [8,1024,1024] f32

    dim3 grid(8 * BPB);   // 512 blocks
    dim3 block(TPB);
    featsim_kernel<<<grid, block>>>(x, lens, w, out);
}